// round 15
// baseline (speedup 1.0000x reference)
#include <cuda_runtime.h>
#include <cuda_fp16.h>
#include <cstdint>
#include <cstddef>

// TargetTokenEncoder with GELU-saturation folding — persistent, fp16 tensor cores.
//   s_j = stats @ w1[:,j] + b1[j]; stats[12]=128 const => most layer-1 columns
//   saturated for ALL rows (per-column interval bound).
//   N cols: h=0 exactly (dropped). P cols: h=s affine -> folded into M[13x256]+v
//   (v exact fp32, carries the dominant output mass).
//   E cols (~45): real GELU -> skinny fp16 m16n8k16 GEMM, K = 13+ecnt rounded
//   to 16 (runtime, template-dispatched).
// NTH=256, ~73KB smem, <=128 regs -> 2 CTAs/SM (occ 50%); W staged once per CTA.

namespace {
constexpr int BATCH  = 65536;
constexpr int DIM    = 256;
constexpr int TM     = 64;             // rows per tile
constexpr int NTILES = BATCH / TM;     // 1024
constexpr int NTH    = 256;            // 8 warps: 2(M) x 4(N)
constexpr int KCAP   = 96;             // max K (13 stats + up to 83 E cols)
constexpr int ECAP   = KCAP - 13;      // 83
constexpr int PW     = 52;             // row pitch in words (104 halves); 52%32==20 -> conflict-free frags
constexpr int SP     = 20;             // stats row pitch (floats)
// dynamic smem layout (bytes)
constexpr int A_BYTES   = TM * PW * 4;     // 13312
constexpr int SCR_BYTES = 15360;           // prologue scratch (covers A region)
constexpr int OFF_A  = 0;
constexpr int OFF_W  = SCR_BYTES;          // W: [n=256][k halves], pitch PW words
constexpr int W_BYTES = DIM * PW * 4;      // 53248
constexpr int OFF_ST = OFF_W + W_BYTES;    // float[TM][SP]
constexpr int OFF_PK = OFF_ST + TM * SP * 4;
constexpr int DYN_BYTES = OFF_PK + TM * 16;   // 74752 (~73KB) -> 2 CTAs/SM
}

__device__ __forceinline__ void mma_f16(float* d, const uint32_t* a, uint32_t b0, uint32_t b1) {
    asm("mma.sync.aligned.m16n8k16.row.col.f32.f16.f16.f32 "
        "{%0,%1,%2,%3}, {%4,%5,%6,%7}, {%8,%9}, {%0,%1,%2,%3};"
        : "+f"(d[0]), "+f"(d[1]), "+f"(d[2]), "+f"(d[3])
        : "r"(a[0]), "r"(a[1]), "r"(a[2]), "r"(a[3]), "r"(b0), "r"(b1));
}

template <int NKS>
__device__ __forceinline__ void run_mma(const uint32_t* __restrict__ Aw,
                                        const uint32_t* __restrict__ Ww,
                                        float acc[2][8][4],
                                        int rbm, int cb, int g, int t) {
#pragma unroll
    for (int ks = 0; ks < NKS; ks++) {
        uint32_t a[2][4];
#pragma unroll
        for (int mt = 0; mt < 2; mt++) {
            const uint32_t* p0 = Aw + (rbm + mt * 16 + g) * PW + ks * 8 + t;
            const uint32_t* p1 = p0 + 8 * PW;
            a[mt][0] = p0[0];
            a[mt][1] = p1[0];
            a[mt][2] = p0[4];
            a[mt][3] = p1[4];
        }
#pragma unroll
        for (int nt = 0; nt < 8; nt++) {
            const uint32_t* q = Ww + (cb + nt * 8 + g) * PW + ks * 8 + t;
            const uint32_t b0 = q[0], b1 = q[4];
            mma_f16(acc[0][nt], a[0], b0, b1);
            mma_f16(acc[1][nt], a[1], b0, b1);
        }
    }
}

__device__ __forceinline__ void acc4(int c, uint32_t& h0, uint32_t& h1, uint32_t& h2) {
    const uint32_t inc = 1u << ((c & 3) << 3);
    if (c < 4) h0 += inc; else if (c < 8) h1 += inc; else h2 += inc;
}

extern "C" __global__ void __launch_bounds__(NTH, 2)
tt_fp16_kernel(const int* __restrict__ y, const float* __restrict__ w1,
               const float* __restrict__ b1, const float* __restrict__ w2,
               const float* __restrict__ b2, float* __restrict__ out)
{
    extern __shared__ char dyn[];
    __half*   A_h   = (__half*)(dyn + OFF_A);     // [TM][104 halves] (pitch PW words)
    __half*   W_h   = (__half*)(dyn + OFF_W);     // [256][104 halves]
    float*    sh_st = (float*)(dyn + OFF_ST);     // [TM][SP]
    uint32_t* sh_pk = (uint32_t*)(dyn + OFF_PK);  // [TM][4]
    const uint32_t* Aw = (const uint32_t*)(dyn + OFF_A);
    const uint32_t* Ww = (const uint32_t*)(dyn + OFF_W);

    __shared__ float s_v[DIM];
    __shared__ float s_w1e[13 * ECAP];
    __shared__ float s_b1e[ECAP];
    __shared__ int   s_pidx[DIM];
    __shared__ int   s_eidx[ECAP];
    __shared__ int   s_cls[DIM];
    __shared__ int   s_cntE[8], s_cntP[8], s_baseE[8], s_baseP[8], s_scal[2];

    const int tid  = threadIdx.x;
    const int lane = tid & 31, warp = tid >> 5;

    // ===================== PROLOGUE =====================
    float* s_w1 = (float*)dyn;            // [14*256] = 14336B (scratch over A region)
    float* s_b1 = (float*)(dyn + 14336);  // [256]

    for (int u = tid; u < 14 * 256; u += NTH) s_w1[u] = w1[u];
    if (tid < 256) s_b1[tid] = b1[tid];
    __syncthreads();

    // classify columns (all 256 threads, warps 0..7)
    {
        const int j = tid;
        float w[14];
#pragma unroll
        for (int k = 0; k < 14; k++) w[k] = s_w1[k * 256 + j];
        const float bj = s_b1[j];
        float wmin = w[0], wmax = w[0];
#pragma unroll
        for (int k = 1; k < 10; k++) { wmin = fminf(wmin, w[k]); wmax = fmaxf(wmax, w[k]); }
        const float c = bj + 128.0f * w[12];
        const float lo = c + wmin + fminf(w[10], 10.0f * w[10]) + fminf(0.0f, 2.303f * w[11])
                           + fminf(0.1f * w[13], w[13]) - 0.01f;
        const float hi = c + wmax + fmaxf(w[10], 10.0f * w[10]) + fmaxf(0.0f, 2.303f * w[11])
                           + fmaxf(0.1f * w[13], w[13]) + 0.01f;
        const bool isP = (lo > 5.6f), isN = (hi < -5.6f);
        const bool isE = !isP && !isN;
        const unsigned mE = __ballot_sync(0xFFFFFFFFu, isE);
        const unsigned mP = __ballot_sync(0xFFFFFFFFu, isP);
        if (lane == 0) { s_cntE[warp] = __popc(mE); s_cntP[warp] = __popc(mP); }
        s_cls[j] = isE ? 2 : (isP ? 1 : 0);
    }
    __syncthreads();
    if (tid == 0) {
        int ae = 0, ap = 0;
        for (int ww = 0; ww < 8; ww++) {
            s_baseE[ww] = ae; ae += s_cntE[ww];
            s_baseP[ww] = ap; ap += s_cntP[ww];
        }
        s_scal[0] = (ae < ECAP) ? ae : ECAP;
        s_scal[1] = ap;
    }
    __syncthreads();
    {
        const int j = tid, cls = s_cls[j];
        const unsigned mE = __ballot_sync(0xFFFFFFFFu, cls == 2);
        const unsigned mP = __ballot_sync(0xFFFFFFFFu, cls == 1);
        const unsigned below = (1u << lane) - 1u;
        if (cls == 2) {
            const int idx = s_baseE[warp] + __popc(mE & below);
            if (idx < ECAP) s_eidx[idx] = j;
        } else if (cls == 1) {
            const int idx = s_baseP[warp] + __popc(mP & below);
            s_pidx[idx] = j;
        }
    }
    __syncthreads();
    const int ecnt = s_scal[0], pcnt = s_scal[1];
    const int nks  = (13 + ecnt + 15) >> 4;   // runtime k-steps (k16 each)

    // fold P columns: thread n accumulates full fixed-order sum (deterministic)
    {
        const int n = tid;
        float accv[13];
#pragma unroll
        for (int m = 0; m < 13; m++) accv[m] = 0.0f;
        float vb = 0.0f;
#pragma unroll 4
        for (int ii = 0; ii < pcnt; ii++) {
            const int jp = s_pidx[ii];
            const float w2v = w2[jp * 256 + n];
#pragma unroll
            for (int m = 0; m < 12; m++) accv[m] += s_w1[m * 256 + jp] * w2v;
            accv[12] += s_w1[13 * 256 + jp] * w2v;         // pmax weight
            vb += (s_b1[jp] + 128.0f * s_w1[12 * 256 + jp]) * w2v;
        }
        __half* Wr = W_h + n * (2 * PW);
#pragma unroll
        for (int m = 0; m < 13; m++) Wr[m] = __float2half_rn(accv[m]);
        s_v[n] = vb + b2[n];
    }
    // E rows of W (zero beyond ecnt, up to ECAP so any nks works)
    for (int u = tid; u < ECAP * 256; u += NTH) {
        const int i = u >> 8, n2 = u & 255;
        const float wv = (i < ecnt) ? w2[s_eidx[i] * 256 + n2] : 0.0f;
        W_h[n2 * (2 * PW) + 13 + i] = __float2half_rn(wv);
    }
    // compact w1 for E (13 features; 128*w12 folded into bias)
    if (tid < ECAP) {
        const bool valid = tid < ecnt;
        const int src = valid ? s_eidx[tid] : 0;
        if (valid) {
#pragma unroll
            for (int k = 0; k < 12; k++) s_w1e[k * ECAP + tid] = s_w1[k * 256 + src];
            s_w1e[12 * ECAP + tid] = s_w1[13 * 256 + src];   // pmax weight
            s_b1e[tid] = s_b1[src] + 128.0f * s_w1[12 * 256 + src];
        } else {
#pragma unroll
            for (int k = 0; k < 13; k++) s_w1e[k * ECAP + tid] = 0.0f;
            s_b1e[tid] = 0.0f;
        }
    }
    __syncthreads();   // prologue scratch (A region) free

    // zero entire A buffer (pad cols stay zero across all tiles)
    for (int u = tid; u < TM * PW; u += NTH) ((uint32_t*)(dyn + OFF_A))[u] = 0u;
    __syncthreads();

    // mma geometry: 8 warps = 2(M) x 4(N), warp tile 32x64
    const int wm = warp >> 2, wn = warp & 3;
    const int g = lane >> 2, t = lane & 3;
    const int rbm = wm * 32, cb = wn * 64;
    const int r_q = tid >> 2, pp_q = tid & 3;   // histogram: 4 threads/row

    // ===================== TILE LOOP =====================
    for (int tile = blockIdx.x; tile < NTILES; tile += gridDim.x) {
        // ---- histogram ----
        {
            const int4* yr = (const int4*)(y + (size_t)(tile * TM + r_q) * 128) + pp_q * 8;
            uint32_t h0 = 0, h1 = 0, h2 = 0;
#pragma unroll
            for (int i = 0; i < 8; i++) {
                int4 v = yr[i];
                acc4(v.x, h0, h1, h2); acc4(v.y, h0, h1, h2);
                acc4(v.z, h0, h1, h2); acc4(v.w, h0, h1, h2);
            }
            h0 += __shfl_xor_sync(0xFFFFFFFFu, h0, 1); h0 += __shfl_xor_sync(0xFFFFFFFFu, h0, 2);
            h1 += __shfl_xor_sync(0xFFFFFFFFu, h1, 1); h1 += __shfl_xor_sync(0xFFFFFFFFu, h1, 2);
            h2 += __shfl_xor_sync(0xFFFFFFFFu, h2, 1); h2 += __shfl_xor_sync(0xFFFFFFFFu, h2, 2);
            if (pp_q == 0) *(uint4*)(sh_pk + r_q * 4) = make_uint4(h0, h1, h2, 0u);
        }
        __syncthreads();

        // ---- stats + A stats columns (fp16) ----
        if (tid < TM) {
            const uint4 pk = *(const uint4*)(sh_pk + tid * 4);
            float* st = sh_st + tid * SP;
            __half* ar = A_h + tid * (2 * PW);
            float nnz = 0.f, ent = 0.f, pmax = 0.f;
#pragma unroll
            for (int c = 0; c < 10; c++) {
                const uint32_t w = (c < 4) ? pk.x : ((c < 8) ? pk.y : pk.z);
                const int cnt = (int)((w >> ((c & 3) * 8)) & 255u);
                const float p = (float)cnt * 0.0078125f;
                st[c] = p;
                ar[c] = __float2half_rn(p);
                if (cnt > 0) nnz += 1.0f;
                ent -= p * __logf(p + 1e-6f);
                pmax = fmaxf(pmax, p);
            }
            st[10] = nnz; st[11] = ent; st[12] = pmax;
            ar[10] = __float2half_rn(nnz);
            ar[11] = __float2half_rn(ent);
            ar[12] = __float2half_rn(pmax);   // 128-const folded into s_v
        }
        __syncthreads();

        // ---- GELU for E columns: thread = (col, row-quarter) ----
        {
            const int i0a = tid >> 2, rb = tid & 3;
#pragma unroll
            for (int pass = 0; pass < 2; pass++) {
                const int i0 = i0a + pass * 64;
                if (i0 >= ecnt) break;
                float w[13];
#pragma unroll
                for (int k = 0; k < 13; k++) w[k] = s_w1e[k * ECAP + i0];
                const float bb = s_b1e[i0];
#pragma unroll
                for (int rr = 0; rr < 16; rr++) {
                    const int r = rb + rr * 4;
                    const float* sp = sh_st + r * SP;
                    float4 s0 = *(const float4*)(sp);
                    float4 s1 = *(const float4*)(sp + 4);
                    float4 s2 = *(const float4*)(sp + 8);
                    float s = bb
                        + s0.x * w[0] + s0.y * w[1] + s0.z * w[2] + s0.w * w[3]
                        + s1.x * w[4] + s1.y * w[5] + s1.z * w[6] + s1.w * w[7]
                        + s2.x * w[8] + s2.y * w[9] + s2.z * w[10] + s2.w * w[11]
                        + sp[12] * w[12];
                    const float u = s * (0.7978845608f + 0.03567740814f * s * s);
                    float th;
                    asm("tanh.approx.f32 %0, %1;" : "=f"(th) : "f"(u));
                    A_h[r * (2 * PW) + 13 + i0] = __float2half_rn(0.5f * s * (1.0f + th));
                }
            }
        }
        __syncthreads();

        // ---- fp16 mma: A[64 x K] @ W[K x 256] + v ----
        float acc[2][8][4];
#pragma unroll
        for (int nt = 0; nt < 8; nt++) {
            float2 vv = *(const float2*)(s_v + cb + nt * 8 + 2 * t);
#pragma unroll
            for (int mt = 0; mt < 2; mt++) {
                acc[mt][nt][0] = vv.x; acc[mt][nt][1] = vv.y;
                acc[mt][nt][2] = vv.x; acc[mt][nt][3] = vv.y;
            }
        }
        switch (nks) {
            case 1: run_mma<1>(Aw, Ww, acc, rbm, cb, g, t); break;
            case 2: run_mma<2>(Aw, Ww, acc, rbm, cb, g, t); break;
            case 3: run_mma<3>(Aw, Ww, acc, rbm, cb, g, t); break;
            case 4: run_mma<4>(Aw, Ww, acc, rbm, cb, g, t); break;
            case 5: run_mma<5>(Aw, Ww, acc, rbm, cb, g, t); break;
            default: run_mma<6>(Aw, Ww, acc, rbm, cb, g, t); break;
        }

        // ---- epilogue ----
        const int row0 = tile * TM;
#pragma unroll
        for (int mt = 0; mt < 2; mt++) {
            float* o0 = out + (size_t)(row0 + rbm + mt * 16 + g) * DIM + cb + 2 * t;
            float* o1 = o0 + 8 * DIM;
#pragma unroll
            for (int nt = 0; nt < 8; nt++) {
                *(float2*)(o0 + nt * 8) = make_float2(acc[mt][nt][0], acc[mt][nt][1]);
                *(float2*)(o1 + nt * 8) = make_float2(acc[mt][nt][2], acc[mt][nt][3]);
            }
        }
        __syncthreads();   // mma reads of A done before next tile's writes
    }
}

extern "C" void kernel_launch(void* const* d_in, const int* in_sizes, int n_in,
                              void* d_out, int out_size) {
    const int*   y  = (const int*)d_in[0];
    const float* w1 = (const float*)d_in[1];
    const float* b1 = (const float*)d_in[2];
    const float* w2 = (const float*)d_in[3];
    const float* b2 = (const float*)d_in[4];
    float* out = (float*)d_out;

    int nsm = 148;
    cudaDeviceGetAttribute(&nsm, cudaDevAttrMultiProcessorCount, 0);
    if (nsm <= 0 || nsm > 1024) nsm = 148;

    cudaFuncSetAttribute(tt_fp16_kernel, cudaFuncAttributeMaxDynamicSharedMemorySize, DYN_BYTES);
    tt_fp16_kernel<<<2 * nsm, NTH, DYN_BYTES>>>(y, w1, b1, w2, b2, out);
}

// round 16
// speedup vs baseline: 1.3468x; 1.3468x over previous
#include <cuda_runtime.h>
#include <cstdint>
#include <cstddef>

// TargetTokenEncoder with GELU-saturation folding.
//   s_j = stats @ w1[:,j] + b1[j]; stats[12]=128 const => most layer-1 cols
//   saturated for ALL rows. N cols: h=0 (dropped). P cols: affine -> folded
//   into M[13x256]+v (v exact fp32). E cols (~45): real GELU -> skinny TF32
//   mma GEMM, K = 13+ecnt rounded to 16 (runtime, template-dispatched).
// Kernels: setup (16 blks, parallel fold) -> main (512 CTAs, 1 tile each,
// cp.async W staging overlapped with hist/stats/GELU).

namespace {
constexpr int BATCH = 65536;
constexpr int DIM   = 256;
constexpr int TM    = 128;    // rows per CTA (main)
constexpr int NTH   = 512;    // 16 warps: 4(M) x 4(N)
constexpr int KFIX  = 96;     // max augmented K
constexpr int ECAP  = KFIX - 13;   // 83
constexpr int AP    = 100;    // sh_A pitch; 100%32==4 -> A frags conflict-free
constexpr int WP    = 264;    // sh_W pitch; 264%32==8 -> B frags conflict-free
constexpr int SP    = 20;     // stats pitch
constexpr int SMEM_WORDS = TM * AP + KFIX * WP + TM * SP + TM * 4;
constexpr int SMEM_BYTES = SMEM_WORDS * 4;   // 164864
}

__device__ int      g_Ecnt;
__device__ int      g_Krt;
__device__ uint32_t g_Wc[KFIX * DIM];   // tf32 bits [K][256]
__device__ float    g_v[DIM];
__device__ float    g_w1e[13 * ECAP];
__device__ float    g_b1e[ECAP];

__device__ __forceinline__ uint32_t f2tf32(float x) {
    uint32_t u;
    asm("cvt.rna.tf32.f32 %0, %1;" : "=r"(u) : "f"(x));
    return u;
}
__device__ __forceinline__ void mma_tf32(float* d,
                                         uint32_t a0, uint32_t a1, uint32_t a2, uint32_t a3,
                                         uint32_t b0, uint32_t b1) {
    asm("mma.sync.aligned.m16n8k8.row.col.f32.tf32.tf32.f32 "
        "{%0,%1,%2,%3}, {%4,%5,%6,%7}, {%8,%9}, {%0,%1,%2,%3};\n"
        : "+f"(d[0]), "+f"(d[1]), "+f"(d[2]), "+f"(d[3])
        : "r"(a0), "r"(a1), "r"(a2), "r"(a3), "r"(b0), "r"(b1));
}
__device__ __forceinline__ void cpasync16(uint32_t dst, const void* src) {
    asm volatile("cp.async.cg.shared.global [%0], [%1], 16;" :: "r"(dst), "l"(src) : "memory");
}
__device__ __forceinline__ uint32_t smem_u32(const void* p) {
    uint32_t a;
    asm("{ .reg .u64 t; cvta.to.shared.u64 t, %1; cvt.u32.u64 %0, t; }" : "=r"(a) : "l"(p));
    return a;
}
__device__ __forceinline__ void acc4(int c, uint32_t& h0, uint32_t& h1, uint32_t& h2) {
    const uint32_t inc = 1u << ((c & 3) << 3);
    if (c < 4) h0 += inc; else if (c < 8) h1 += inc; else h2 += inc;
}

template <int NKS>
__device__ __forceinline__ void run_mma(const uint32_t* __restrict__ A,
                                        const uint32_t* __restrict__ W,
                                        float acc[2][8][4],
                                        int rbm, int cb, int g, int t) {
#pragma unroll
    for (int ks = 0; ks < NKS; ks++) {
        const int kb = ks * 8;
        uint32_t a[2][4];
#pragma unroll
        for (int mt = 0; mt < 2; mt++) {
            const uint32_t* p0 = A + (rbm + mt * 16 + g) * AP + kb + t;
            const uint32_t* p1 = p0 + 8 * AP;
            a[mt][0] = p0[0];
            a[mt][1] = p1[0];
            a[mt][2] = p0[4];
            a[mt][3] = p1[4];
        }
#pragma unroll
        for (int nt = 0; nt < 8; nt++) {
            const int cc = cb + nt * 8 + g;
            const uint32_t b0  = W[(kb + t) * WP + cc];
            const uint32_t b1v = W[(kb + t + 4) * WP + cc];
            mma_tf32(acc[0][nt], a[0][0], a[0][1], a[0][2], a[0][3], b0, b1v);
            mma_tf32(acc[1][nt], a[1][0], a[1][1], a[1][2], a[1][3], b0, b1v);
        }
    }
}

// ---------------------------------------------------------------------------
// Setup: 16 blocks x 256 threads. Each block classifies (redundant) and folds
// 16 output columns (16-way chunk split, fixed-order reduce -> deterministic).
// ---------------------------------------------------------------------------
__global__ void tt_setup_kernel(const float* __restrict__ w1, const float* __restrict__ b1,
                                const float* __restrict__ w2, const float* __restrict__ b2)
{
    __shared__ float s_w1[14 * 256];
    __shared__ float s_b1[256];
    __shared__ float s_part[16][16][14];
    __shared__ int   s_pidx[256];
    __shared__ int   s_eidx[ECAP];
    __shared__ int   s_cls[256];
    __shared__ int   s_cntE[8], s_cntP[8], s_baseE[8], s_baseP[8], s_scal[2];

    const int tid = threadIdx.x;
    const int lane = tid & 31, warp = tid >> 5;

    for (int u = tid; u < 14 * 256; u += 256) s_w1[u] = w1[u];
    s_b1[tid] = b1[tid];
    __syncthreads();

    // classify
    {
        const int j = tid;
        float w[14];
#pragma unroll
        for (int k = 0; k < 14; k++) w[k] = s_w1[k * 256 + j];
        const float bj = s_b1[j];
        float wmin = w[0], wmax = w[0];
#pragma unroll
        for (int k = 1; k < 10; k++) { wmin = fminf(wmin, w[k]); wmax = fmaxf(wmax, w[k]); }
        const float c = bj + 128.0f * w[12];
        const float lo = c + wmin + fminf(w[10], 10.0f * w[10]) + fminf(0.0f, 2.303f * w[11])
                           + fminf(0.1f * w[13], w[13]) - 0.01f;
        const float hi = c + wmax + fmaxf(w[10], 10.0f * w[10]) + fmaxf(0.0f, 2.303f * w[11])
                           + fmaxf(0.1f * w[13], w[13]) + 0.01f;
        const bool isP = (lo > 5.6f), isN = (hi < -5.6f);
        const bool isE = !isP && !isN;
        const unsigned mE = __ballot_sync(0xFFFFFFFFu, isE);
        const unsigned mP = __ballot_sync(0xFFFFFFFFu, isP);
        if (lane == 0) { s_cntE[warp] = __popc(mE); s_cntP[warp] = __popc(mP); }
        s_cls[j] = isE ? 2 : (isP ? 1 : 0);
    }
    __syncthreads();
    if (tid == 0) {
        int ae = 0, ap = 0;
        for (int ww = 0; ww < 8; ww++) {
            s_baseE[ww] = ae; ae += s_cntE[ww];
            s_baseP[ww] = ap; ap += s_cntP[ww];
        }
        s_scal[0] = (ae < ECAP) ? ae : ECAP;
        s_scal[1] = ap;
    }
    __syncthreads();
    {
        const int j = tid, cls = s_cls[j];
        const unsigned mE = __ballot_sync(0xFFFFFFFFu, cls == 2);
        const unsigned mP = __ballot_sync(0xFFFFFFFFu, cls == 1);
        const unsigned below = (1u << lane) - 1u;
        if (cls == 2) {
            const int idx = s_baseE[warp] + __popc(mE & below);
            if (idx < ECAP) s_eidx[idx] = j;
        } else if (cls == 1) {
            const int idx = s_baseP[warp] + __popc(mP & below);
            s_pidx[idx] = j;
        }
    }
    __syncthreads();
    const int ecnt = s_scal[0], pcnt = s_scal[1];
    int nks = (13 + ecnt + 7) >> 3;
    nks = (nks + 1) & ~1;                 // round up to even (K multiple of 16)
    if (nks < 2) nks = 2;
    if (nks > 12) nks = 12;
    const int krt = nks * 8;

    // fold: 16 n-columns per block, 16 chunks each
    {
        const int n_local = tid >> 4, chunk = tid & 15;
        const int n = blockIdx.x * 16 + n_local;
        float acc[13];
#pragma unroll
        for (int m = 0; m < 13; m++) acc[m] = 0.0f;
        float vb = 0.0f;
        for (int ii = chunk; ii < pcnt; ii += 16) {
            const int jp = s_pidx[ii];
            const float w2v = w2[jp * 256 + n];
#pragma unroll
            for (int m = 0; m < 12; m++) acc[m] += s_w1[m * 256 + jp] * w2v;
            acc[12] += s_w1[13 * 256 + jp] * w2v;          // pmax weight
            vb += (s_b1[jp] + 128.0f * s_w1[12 * 256 + jp]) * w2v;
        }
        float* pp = s_part[n_local][chunk];
#pragma unroll
        for (int m = 0; m < 13; m++) pp[m] = acc[m];
        pp[13] = vb;
    }
    __syncthreads();
    if ((tid & 15) == 0) {
        const int n_local = tid >> 4;
        const int n = blockIdx.x * 16 + n_local;
        float tot[14];
#pragma unroll
        for (int m = 0; m < 14; m++) tot[m] = s_part[n_local][0][m];
        for (int cc = 1; cc < 16; cc++)            // fixed order -> deterministic
#pragma unroll
            for (int m = 0; m < 14; m++) tot[m] += s_part[n_local][cc][m];
#pragma unroll
        for (int m = 0; m < 13; m++) g_Wc[m * 256 + n] = f2tf32(tot[m]);
        g_v[n] = tot[13] + b2[n];
    }

    // E rows (zero-pad to krt) for this block's n-range
    for (int u = tid; u < (krt - 13) * 16; u += 256) {
        const int i = u >> 4, nl = u & 15;
        const int n = blockIdx.x * 16 + nl;
        const float wv = (i < ecnt) ? w2[s_eidx[i] * 256 + n] : 0.0f;
        g_Wc[(13 + i) * 256 + n] = f2tf32(wv);
    }

    if (blockIdx.x == 0) {
        if (tid < ECAP) {
            const bool valid = tid < ecnt;
            const int src = valid ? s_eidx[tid] : 0;
            if (valid) {
#pragma unroll
                for (int k = 0; k < 12; k++) g_w1e[k * ECAP + tid] = s_w1[k * 256 + src];
                g_w1e[12 * ECAP + tid] = s_w1[13 * 256 + src];    // pmax weight
                g_b1e[tid] = s_b1[src] + 128.0f * s_w1[12 * 256 + src];
            } else {
#pragma unroll
                for (int k = 0; k < 13; k++) g_w1e[k * ECAP + tid] = 0.0f;
                g_b1e[tid] = 0.0f;
            }
        }
        if (tid == 0) { g_Ecnt = ecnt; g_Krt = krt; }
    }
}

// ---------------------------------------------------------------------------
// Main: 512 CTAs x 512 threads, one 128-row tile each. cp.async W staging
// overlaps hist + stats + GELU; TF32 mma with runtime-K dispatch.
// ---------------------------------------------------------------------------
extern "C" __global__ void __launch_bounds__(NTH, 1)
tt_main_kernel(const int* __restrict__ y, float* __restrict__ out)
{
    extern __shared__ uint32_t smem[];
    uint32_t* sh_A  = smem;                                  // [TM][AP]
    uint32_t* sh_W  = smem + TM * AP;                        // [KFIX][WP]
    float*    sh_st = (float*)(smem + TM * AP + KFIX * WP);  // [TM][SP]
    uint32_t* sh_pk = (uint32_t*)(sh_st + TM * SP);          // [TM][4]

    const int tid  = threadIdx.x;
    const int lane = tid & 31, warp = tid >> 5;
    const int row0 = blockIdx.x * TM;
    const int Krt  = g_Krt;
    const int Ecnt = g_Ecnt;
    const int nks  = Krt >> 3;

    // mma geometry
    const int wm = warp >> 2, wn = warp & 3;
    const int g = lane >> 2, t = lane & 3;
    const int rbm = wm * 32, cb = wn * 64;

    // folded bias prefetch (registers; L2-hot)
    float2 vv[8];
#pragma unroll
    for (int nt = 0; nt < 8; nt++) vv[nt] = *(const float2*)(g_v + cb + nt * 8 + 2 * t);

    // ---- stage W via cp.async (fire-and-forget; waited just before mma) ----
    {
        const uint32_t wbase = smem_u32(sh_W);
        const int items = Krt * 64;
        for (int u = tid; u < items; u += NTH) {
            const int row = u >> 6, c4 = u & 63;
            cpasync16(wbase + (uint32_t)(row * WP + c4 * 4) * 4, g_Wc + row * 256 + c4 * 4);
        }
        asm volatile("cp.async.commit_group;" ::: "memory");
    }

    // ---- histogram: 4 threads/row, shfl-reduced ----
    const int r_q = tid >> 2, pp_q = tid & 3;
    {
        const int4* yr = (const int4*)(y + (size_t)(row0 + r_q) * 128) + pp_q * 8;
        uint32_t h0 = 0, h1 = 0, h2 = 0;
#pragma unroll
        for (int i = 0; i < 8; i++) {
            int4 v = yr[i];
            acc4(v.x, h0, h1, h2); acc4(v.y, h0, h1, h2);
            acc4(v.z, h0, h1, h2); acc4(v.w, h0, h1, h2);
        }
        h0 += __shfl_xor_sync(0xFFFFFFFFu, h0, 1); h0 += __shfl_xor_sync(0xFFFFFFFFu, h0, 2);
        h1 += __shfl_xor_sync(0xFFFFFFFFu, h1, 1); h1 += __shfl_xor_sync(0xFFFFFFFFu, h1, 2);
        h2 += __shfl_xor_sync(0xFFFFFFFFu, h2, 1); h2 += __shfl_xor_sync(0xFFFFFFFFu, h2, 2);
        if (pp_q == 0) *(uint4*)(sh_pk + r_q * 4) = make_uint4(h0, h1, h2, 0u);
    }
    __syncthreads();

    // ---- stats + A stats columns ----
    if (tid < TM) {
        const uint4 pk = *(const uint4*)(sh_pk + tid * 4);
        float* st = sh_st + tid * SP;
        uint32_t* ar = sh_A + tid * AP;
        float nnz = 0.f, ent = 0.f, pmax = 0.f;
#pragma unroll
        for (int c = 0; c < 10; c++) {
            const uint32_t w = (c < 4) ? pk.x : ((c < 8) ? pk.y : pk.z);
            const int cnt = (int)((w >> ((c & 3) * 8)) & 255u);
            const float p = (float)cnt * 0.0078125f;
            st[c] = p;
            ar[c] = f2tf32(p);
            if (cnt > 0) nnz += 1.0f;
            ent -= p * __logf(p + 1e-6f);
            pmax = fmaxf(pmax, p);
        }
        st[10] = nnz; st[11] = ent; st[12] = pmax;
        ar[10] = f2tf32(nnz);
        ar[11] = f2tf32(ent);
        ar[12] = f2tf32(pmax);   // 128-const folded into g_v
    }
    __syncthreads();

    // ---- GELU for E columns (zero-pad to Krt-13): thread=(col, row-octant) ----
    {
        const int rb = tid & 7;
        const int nE = Krt - 13;
#pragma unroll
        for (int pass = 0; pass < 2; pass++) {
            const int i0 = (tid >> 3) + pass * 64;
            if (i0 >= nE) break;
            const bool valid = i0 < Ecnt;
            float w[13], bb = 0.0f;
            if (valid) {
#pragma unroll
                for (int k = 0; k < 13; k++) w[k] = g_w1e[k * ECAP + i0];
                bb = g_b1e[i0];
            }
#pragma unroll
            for (int rr = 0; rr < 16; rr++) {
                const int r = rb + rr * 8;
                uint32_t hbits = 0u;
                if (valid) {
                    const float* sp = sh_st + r * SP;
                    float4 s0 = *(const float4*)(sp);
                    float4 s1 = *(const float4*)(sp + 4);
                    float4 s2 = *(const float4*)(sp + 8);
                    float s = bb
                        + s0.x * w[0] + s0.y * w[1] + s0.z * w[2] + s0.w * w[3]
                        + s1.x * w[4] + s1.y * w[5] + s1.z * w[6] + s1.w * w[7]
                        + s2.x * w[8] + s2.y * w[9] + s2.z * w[10] + s2.w * w[11]
                        + sp[12] * w[12];
                    const float u = s * (0.7978845608f + 0.03567740814f * s * s);
                    float th;
                    asm("tanh.approx.f32 %0, %1;" : "=f"(th) : "f"(u));
                    hbits = f2tf32(0.5f * s * (1.0f + th));
                }
                sh_A[r * AP + 13 + i0] = hbits;
            }
        }
    }

    // ---- wait W staging, then mma ----
    asm volatile("cp.async.wait_group 0;" ::: "memory");
    __syncthreads();

    float acc[2][8][4];
#pragma unroll
    for (int nt = 0; nt < 8; nt++) {
#pragma unroll
        for (int mt = 0; mt < 2; mt++) {
            acc[mt][nt][0] = vv[nt].x; acc[mt][nt][1] = vv[nt].y;
            acc[mt][nt][2] = vv[nt].x; acc[mt][nt][3] = vv[nt].y;
        }
    }
    switch (nks) {
        case 2:  run_mma<2>(sh_A, sh_W, acc, rbm, cb, g, t); break;
        case 4:  run_mma<4>(sh_A, sh_W, acc, rbm, cb, g, t); break;
        case 6:  run_mma<6>(sh_A, sh_W, acc, rbm, cb, g, t); break;
        case 8:  run_mma<8>(sh_A, sh_W, acc, rbm, cb, g, t); break;
        case 10: run_mma<10>(sh_A, sh_W, acc, rbm, cb, g, t); break;
        default: run_mma<12>(sh_A, sh_W, acc, rbm, cb, g, t); break;
    }

    // ---- epilogue ----
#pragma unroll
    for (int mt = 0; mt < 2; mt++) {
        float* o0 = out + (size_t)(row0 + rbm + mt * 16 + g) * DIM + cb + 2 * t;
        float* o1 = o0 + 8 * DIM;
#pragma unroll
        for (int nt = 0; nt < 8; nt++) {
            *(float2*)(o0 + nt * 8) = make_float2(acc[mt][nt][0], acc[mt][nt][1]);
            *(float2*)(o1 + nt * 8) = make_float2(acc[mt][nt][2], acc[mt][nt][3]);
        }
    }
}

extern "C" void kernel_launch(void* const* d_in, const int* in_sizes, int n_in,
                              void* d_out, int out_size) {
    const int*   y  = (const int*)d_in[0];
    const float* w1 = (const float*)d_in[1];
    const float* b1 = (const float*)d_in[2];
    const float* w2 = (const float*)d_in[3];
    const float* b2 = (const float*)d_in[4];
    float* out = (float*)d_out;

    cudaFuncSetAttribute(tt_main_kernel, cudaFuncAttributeMaxDynamicSharedMemorySize, SMEM_BYTES);
    tt_setup_kernel<<<16, 256>>>(w1, b1, w2, b2);
    tt_main_kernel<<<BATCH / TM, NTH, SMEM_BYTES>>>(y, out);
}